// round 6
// baseline (speedup 1.0000x reference)
#include <cuda_runtime.h>
#include <cuda_bf16.h>
#include <cstdint>

#define CUBE_L   512
#define EQU_H    1024
#define EQU_W    2048
#define E_COUNT  4
#define CHANNELS 3
#define PLANE    (CUBE_L * CUBE_L)      // 262144
#define NPIX     (EQU_H * EQU_W)        // 2097152

#define TILE_W   32
#define TILE_H   32

// 2D-tiled mapping: each 1024-thread block covers a 32(w) x 32(h) equirect
// tile. Warp = 32 consecutive pixels along w (max intra-warp gather
// coherence); the 32 rows of the tile share cube-face tap rows in L1
// (adjacent equirect rows' bilinear windows overlap ~50-100%).
// regs=32 x 2048 threads/SM fills the register file exactly -> 64 warps/SM.
__global__ __launch_bounds__(TILE_W * TILE_H) void cube2equirec_kernel(
    const float* __restrict__ x,        // (E*6, C, L, L)
    const float* __restrict__ uv,       // (H, W, 2)
    const int*   __restrict__ face_idx, // (H, W)
    float*       __restrict__ out)      // (E, C, H, W)
{
    const int w = blockIdx.x * TILE_W + (threadIdx.x & (TILE_W - 1));
    const int h = blockIdx.y * TILE_H + (threadIdx.x >> 5);
    const int p = h * EQU_W + w;

    // LUT loads (read exactly once per pixel across whole kernel)
    const float2 uvp = __ldcs(reinterpret_cast<const float2*>(uv) + p);
    const int f = __ldcs(face_idx + p);

    const float u = uvp.x;
    const float v = uvp.y;

    int x0 = (int)floorf(u);
    int y0 = (int)floorf(v);
    x0 = min(max(x0, 0), CUBE_L - 1);
    y0 = min(max(y0, 0), CUBE_L - 1);
    const int x1 = min(x0 + 1, CUBE_L - 1);
    const int y1 = min(y0 + 1, CUBE_L - 1);

    const float wx = u - (float)x0;
    const float wy = v - (float)y0;
    const float w00 = (1.0f - wx) * (1.0f - wy);
    const float w01 = wx * (1.0f - wy);
    const float w10 = (1.0f - wx) * wy;
    const float w11 = wx * wy;

    const int o00 = y0 * CUBE_L + x0;
    const int o01 = y0 * CUBE_L + x1;
    const int o10 = y1 * CUBE_L + x0;
    const int o11 = y1 * CUBE_L + x1;

    #pragma unroll
    for (int e = 0; e < E_COUNT; ++e) {
        const float* __restrict__ face_base =
            x + (size_t)((e * 6 + f) * CHANNELS) * PLANE;
        #pragma unroll
        for (int c = 0; c < CHANNELS; ++c) {
            const float* __restrict__ b = face_base + (size_t)c * PLANE;
            const float g00 = __ldg(b + o00);
            const float g01 = __ldg(b + o01);
            const float g10 = __ldg(b + o10);
            const float g11 = __ldg(b + o11);
            const float val = g00 * w00 + g01 * w01 + g10 * w10 + g11 * w11;
            __stcs(out + (size_t)(e * CHANNELS + c) * NPIX + p, val);
        }
    }
}

extern "C" void kernel_launch(void* const* d_in, const int* in_sizes, int n_in,
                              void* d_out, int out_size)
{
    const float* x        = (const float*)d_in[0];
    const float* uv       = (const float*)d_in[1];
    const int*   face_idx = (const int*)d_in[2];
    float*       out      = (float*)d_out;

    dim3 block(TILE_W * TILE_H);                      // 1024 threads
    dim3 grid(EQU_W / TILE_W, EQU_H / TILE_H);        // 64 x 32
    cube2equirec_kernel<<<grid, block>>>(x, uv, face_idx, out);
}

// round 7
// speedup vs baseline: 1.0732x; 1.0732x over previous
#include <cuda_runtime.h>
#include <cuda_bf16.h>
#include <cstdint>

#define CUBE_L   512
#define EQU_H    1024
#define EQU_W    2048
#define E_COUNT  4
#define CHANNELS 3
#define NPLANES  (E_COUNT * CHANNELS)   // 12
#define PLANE    (CUBE_L * CUBE_L)      // 262144
#define NPIX     (EQU_H * EQU_W)        // 2097152

#define TILE_W   32
#define TILE_H   16

// R5 winning shape (512-thread 32x16 tiles, warp = 32 px along w) plus a
// 2-plane software pipeline: while blending/storing plane k, plane k+1's
// 4 taps are already in flight. __launch_bounds__(512,3) licenses ~42 regs
// so ptxas keeps both tap sets live (MLP 4 -> 8 per warp, 48 warps/SM).
__global__ __launch_bounds__(TILE_W * TILE_H, 3) void cube2equirec_kernel(
    const float* __restrict__ x,        // (E*6, C, L, L)
    const float* __restrict__ uv,       // (H, W, 2)
    const int*   __restrict__ face_idx, // (H, W)
    float*       __restrict__ out)      // (E, C, H, W)
{
    const int w = blockIdx.x * TILE_W + (threadIdx.x & (TILE_W - 1));
    const int h = blockIdx.y * TILE_H + (threadIdx.x >> 5);
    const int p = h * EQU_W + w;

    const float2 uvp = __ldcs(reinterpret_cast<const float2*>(uv) + p);
    const int f = __ldcs(face_idx + p);

    const float u = uvp.x;
    const float v = uvp.y;

    int x0 = (int)floorf(u);
    int y0 = (int)floorf(v);
    x0 = min(max(x0, 0), CUBE_L - 1);
    y0 = min(max(y0, 0), CUBE_L - 1);
    const int x1 = min(x0 + 1, CUBE_L - 1);
    const int y1 = min(y0 + 1, CUBE_L - 1);

    const float wx = u - (float)x0;
    const float wy = v - (float)y0;
    const float w00 = (1.0f - wx) * (1.0f - wy);
    const float w01 = wx * (1.0f - wy);
    const float w10 = (1.0f - wx) * wy;
    const float w11 = wx * wy;

    const int o00 = y0 * CUBE_L + x0;
    const int o01 = y0 * CUBE_L + x1;
    const int o10 = y1 * CUBE_L + x0;
    const int o11 = y1 * CUBE_L + x1;

    // Plane k = e*CHANNELS + c lives at x + (18e + 3f + c)*PLANE.
    // Walk k = 0..11 with a precomputed base-pointer step pattern:
    // step within e: +PLANE; step across e (c wraps 2->0): +16*PLANE.
    const float* __restrict__ b = x + (size_t)(3 * f) * PLANE;

    float a00, a01, a10, a11;   // current plane taps
    float n00, n01, n10, n11;   // next plane taps (in flight)

    // Prologue: plane 0
    a00 = __ldg(b + o00); a01 = __ldg(b + o01);
    a10 = __ldg(b + o10); a11 = __ldg(b + o11);

    #pragma unroll
    for (int k = 0; k < NPLANES; ++k) {
        // Kick off plane k+1 loads before consuming plane k.
        if (k + 1 < NPLANES) {
            const int e1 = (k + 1) / CHANNELS;
            const int c1 = (k + 1) % CHANNELS;
            const float* __restrict__ bn = b + (size_t)(18 * e1 + c1) * PLANE;
            n00 = __ldg(bn + o00); n01 = __ldg(bn + o01);
            n10 = __ldg(bn + o10); n11 = __ldg(bn + o11);
        }
        const float val = a00 * w00 + a01 * w01 + a10 * w10 + a11 * w11;
        __stcs(out + (size_t)k * NPIX + p, val);
        a00 = n00; a01 = n01; a10 = n10; a11 = n11;
    }
}

extern "C" void kernel_launch(void* const* d_in, const int* in_sizes, int n_in,
                              void* d_out, int out_size)
{
    const float* x        = (const float*)d_in[0];
    const float* uv       = (const float*)d_in[1];
    const int*   face_idx = (const int*)d_in[2];
    float*       out      = (float*)d_out;

    dim3 block(TILE_W * TILE_H);                      // 512 threads
    dim3 grid(EQU_W / TILE_W, EQU_H / TILE_H);        // 64 x 64
    cube2equirec_kernel<<<grid, block>>>(x, uv, face_idx, out);
}

// round 8
// speedup vs baseline: 1.0813x; 1.0075x over previous
#include <cuda_runtime.h>
#include <cuda_bf16.h>
#include <cstdint>

#define CUBE_L   512
#define EQU_H    1024
#define EQU_W    2048
#define E_COUNT  4
#define CHANNELS 3
#define NPLANES  (E_COUNT * CHANNELS)   // 12
#define PLANE    (CUBE_L * CUBE_L)      // 262144
#define NPIX     (EQU_H * EQU_W)        // 2097152

#define TILE_W   32
#define TILE_H   8

// Winning shape: 1 px/thread, warp = 32 consecutive px along w (max gather
// coherence), 2D tile for vertical tap reuse in L1, depth-2 plane pipeline
// (8 loads in flight/warp). 256-thread CTAs with (256,6) bounds: 6 CTAs/SM,
// 48 warps, fine-grained scheduling, small tails.
__global__ __launch_bounds__(TILE_W * TILE_H, 6) void cube2equirec_kernel(
    const float* __restrict__ x,        // (E*6, C, L, L)
    const float* __restrict__ uv,       // (H, W, 2)
    const int*   __restrict__ face_idx, // (H, W)
    float*       __restrict__ out)      // (E, C, H, W)
{
    const int w = blockIdx.x * TILE_W + (threadIdx.x & (TILE_W - 1));
    const int h = blockIdx.y * TILE_H + (threadIdx.x >> 5);
    const int p = h * EQU_W + w;

    const float2 uvp = __ldcs(reinterpret_cast<const float2*>(uv) + p);
    const int f = __ldcs(face_idx + p);

    const float u = uvp.x;
    const float v = uvp.y;

    int x0 = (int)floorf(u);
    int y0 = (int)floorf(v);
    x0 = min(max(x0, 0), CUBE_L - 1);
    y0 = min(max(y0, 0), CUBE_L - 1);
    const int x1 = min(x0 + 1, CUBE_L - 1);
    const int y1 = min(y0 + 1, CUBE_L - 1);

    const float wx = u - (float)x0;
    const float wy = v - (float)y0;
    const float w00 = (1.0f - wx) * (1.0f - wy);
    const float w01 = wx * (1.0f - wy);
    const float w10 = (1.0f - wx) * wy;
    const float w11 = wx * wy;

    const int o00 = y0 * CUBE_L + x0;
    const int o01 = y0 * CUBE_L + x1;
    const int o10 = y1 * CUBE_L + x0;
    const int o11 = y1 * CUBE_L + x1;

    // Plane k = e*CHANNELS + c lives at x + (18e + 3f + c)*PLANE.
    const float* __restrict__ b = x + (size_t)(3 * f) * PLANE;

    float a00, a01, a10, a11;   // current plane taps
    float n00, n01, n10, n11;   // next plane taps (in flight)

    // Prologue: plane 0
    a00 = __ldg(b + o00); a01 = __ldg(b + o01);
    a10 = __ldg(b + o10); a11 = __ldg(b + o11);

    #pragma unroll
    for (int k = 0; k < NPLANES; ++k) {
        if (k + 1 < NPLANES) {
            const int e1 = (k + 1) / CHANNELS;
            const int c1 = (k + 1) % CHANNELS;
            const float* __restrict__ bn = b + (size_t)(18 * e1 + c1) * PLANE;
            n00 = __ldg(bn + o00); n01 = __ldg(bn + o01);
            n10 = __ldg(bn + o10); n11 = __ldg(bn + o11);
        }
        const float val = a00 * w00 + a01 * w01 + a10 * w10 + a11 * w11;
        __stcs(out + (size_t)k * NPIX + p, val);
        a00 = n00; a01 = n01; a10 = n10; a11 = n11;
    }
}

extern "C" void kernel_launch(void* const* d_in, const int* in_sizes, int n_in,
                              void* d_out, int out_size)
{
    const float* x        = (const float*)d_in[0];
    const float* uv       = (const float*)d_in[1];
    const int*   face_idx = (const int*)d_in[2];
    float*       out      = (float*)d_out;

    dim3 block(TILE_W * TILE_H);                      // 256 threads
    dim3 grid(EQU_W / TILE_W, EQU_H / TILE_H);        // 64 x 128 = 8192
    cube2equirec_kernel<<<grid, block>>>(x, uv, face_idx, out);
}

// round 10
// speedup vs baseline: 1.1106x; 1.0271x over previous
#include <cuda_runtime.h>
#include <cuda_bf16.h>
#include <cstdint>

#define CUBE_L   512
#define EQU_H    1024
#define EQU_W    2048
#define E_COUNT  4
#define CHANNELS 3
#define NPLANES  (E_COUNT * CHANNELS)   // 12
#define PLANE    (CUBE_L * CUBE_L)      // 262144
#define NPIX     (EQU_H * EQU_W)        // 2097152

#define TILE_W   32
#define TILE_H   8

// Element offset of plane k's base relative to x + 3f*PLANE.
// k = e*CHANNELS + c  ->  (18e + c) * PLANE. Folds to an immediate when k
// is a compile-time constant (fully unrolled loop).
__device__ __forceinline__ constexpr size_t poff(int k) {
    return (size_t)(18 * (k / CHANNELS) + (k % CHANNELS)) * PLANE;
}

// Winning shape: 1 px/thread, warp = 32 consecutive px along w, 32x8 tiles
// for vertical L1 tap reuse. Depth-3 plane pipeline: taps for planes k, k+1,
// k+2 are in flight simultaneously (12 loads/warp outstanding).
__global__ __launch_bounds__(TILE_W * TILE_H, 5) void cube2equirec_kernel(
    const float* __restrict__ x,        // (E*6, C, L, L)
    const float* __restrict__ uv,       // (H, W, 2)
    const int*   __restrict__ face_idx, // (H, W)
    float*       __restrict__ out)      // (E, C, H, W)
{
    const int w = blockIdx.x * TILE_W + (threadIdx.x & (TILE_W - 1));
    const int h = blockIdx.y * TILE_H + (threadIdx.x >> 5);
    const int p = h * EQU_W + w;

    const float2 uvp = __ldcs(reinterpret_cast<const float2*>(uv) + p);
    const int f = __ldcs(face_idx + p);

    const float u = uvp.x;
    const float v = uvp.y;

    int x0 = (int)floorf(u);
    int y0 = (int)floorf(v);
    x0 = min(max(x0, 0), CUBE_L - 1);
    y0 = min(max(y0, 0), CUBE_L - 1);
    const int x1 = min(x0 + 1, CUBE_L - 1);
    const int y1 = min(y0 + 1, CUBE_L - 1);

    const float wx = u - (float)x0;
    const float wy = v - (float)y0;
    const float w00 = (1.0f - wx) * (1.0f - wy);
    const float w01 = wx * (1.0f - wy);
    const float w10 = (1.0f - wx) * wy;
    const float w11 = wx * wy;

    const int o00 = y0 * CUBE_L + x0;
    const int o01 = y0 * CUBE_L + x1;
    const int o10 = y1 * CUBE_L + x0;
    const int o11 = y1 * CUBE_L + x1;

    // Plane k = e*CHANNELS + c lives at x + (18e + 3f + c)*PLANE.
    const float* __restrict__ b = x + (size_t)(3 * f) * PLANE;

    // Depth-3 rotating buffers
    float g0[4], g1[4], g2[4];

    {   // Prologue: planes 0 and 1 in flight
        const float* b0 = b + poff(0);
        g0[0] = __ldg(b0 + o00); g0[1] = __ldg(b0 + o01);
        g0[2] = __ldg(b0 + o10); g0[3] = __ldg(b0 + o11);
        const float* b1 = b + poff(1);
        g1[0] = __ldg(b1 + o00); g1[1] = __ldg(b1 + o01);
        g1[2] = __ldg(b1 + o10); g1[3] = __ldg(b1 + o11);
    }

    #pragma unroll
    for (int k = 0; k < NPLANES; ++k) {
        // Kick off plane k+2 before consuming plane k.
        if (k + 2 < NPLANES) {
            const float* bn = b + poff(k + 2);
            g2[0] = __ldg(bn + o00); g2[1] = __ldg(bn + o01);
            g2[2] = __ldg(bn + o10); g2[3] = __ldg(bn + o11);
        }
        const float val = g0[0] * w00 + g0[1] * w01 + g0[2] * w10 + g0[3] * w11;
        __stcs(out + (size_t)k * NPIX + p, val);
        // rotate buffers
        g0[0] = g1[0]; g0[1] = g1[1]; g0[2] = g1[2]; g0[3] = g1[3];
        g1[0] = g2[0]; g1[1] = g2[1]; g1[2] = g2[2]; g1[3] = g2[3];
    }
}

extern "C" void kernel_launch(void* const* d_in, const int* in_sizes, int n_in,
                              void* d_out, int out_size)
{
    const float* x        = (const float*)d_in[0];
    const float* uv       = (const float*)d_in[1];
    const int*   face_idx = (const int*)d_in[2];
    float*       out      = (float*)d_out;

    dim3 block(TILE_W * TILE_H);                      // 256 threads
    dim3 grid(EQU_W / TILE_W, EQU_H / TILE_H);        // 64 x 128 = 8192
    cube2equirec_kernel<<<grid, block>>>(x, uv, face_idx, out);
}